// round 8
// baseline (speedup 1.0000x reference)
#include <cuda_runtime.h>
#include <cuda_fp16.h>

// ---------------------------------------------------------------------------
// SimpleGCN, sm_100a. fp32 compute, fp16 messages AND activations.
//   s[n] = fp16( (h_in @ W)[n] * dis[n] )            k_gemm   (g_h/x -> g_s)
//   h[v] = fp16( relu( (s[v]+sum s[u]) * dis + b ) ) k_gather (g_s -> g_h)
// CSR gather (no hot-path atomics). gemm0 overlapped with CSR build via
// stream fork/join. GEMM: 4 threads/node for high occupancy.
// ---------------------------------------------------------------------------

#define NN 100000
#define EE 1600000
#define GG 64

__device__ float  g_dis [NN];
__device__ int    g_degi[NN];
__device__ int    g_rowptr[NN + 1];
__device__ int    g_cursor[NN];
__device__ int    g_bsum[512];
__device__ int    g_csr[EE];
__device__ __half g_s [NN * 64];      // fp16 message rows (gemm out)
__device__ __half g_h [NN * 64];      // fp16 activations   (gather out)
__device__ float  g_pool[GG * 64];

// --------------------------- zero (degi + pool) ----------------------------
__global__ void k_zero(int n) {
    int i = blockIdx.x * blockDim.x + threadIdx.x;
    if (i < n) g_degi[i] = 0;
    if (i < GG * 64) g_pool[i] = 0.0f;
}

// --------------------------- degree count (4 edges/thread) -----------------
__global__ void k_degc(const int* __restrict__ dst, int e) {
    int i = (blockIdx.x * blockDim.x + threadIdx.x) * 4;
    if (i + 3 < e) {
        int4 d = *reinterpret_cast<const int4*>(dst + i);
        atomicAdd(&g_degi[d.x], 1);
        atomicAdd(&g_degi[d.y], 1);
        atomicAdd(&g_degi[d.z], 1);
        atomicAdd(&g_degi[d.w], 1);
    } else {
        for (; i < e; i++) atomicAdd(&g_degi[dst[i]], 1);
    }
}

// --------------------------- scan1: block-local scan + dis -----------------
__global__ void k_scan1(int n) {
    __shared__ int s[256];
    int b = blockIdx.x, t = threadIdx.x;
    int i = b * 256 + t;
    int v = (i < n) ? g_degi[i] : 0;
    if (i < n) g_dis[i] = rsqrtf((float)v + 1.0f);
    s[t] = v;
    __syncthreads();
#pragma unroll
    for (int off = 1; off < 256; off <<= 1) {
        int add = (t >= off) ? s[t - off] : 0;
        __syncthreads();
        s[t] += add;
        __syncthreads();
    }
    if (i < n) g_rowptr[i] = s[t] - v;
    if (t == 255) g_bsum[b] = s[255];
}

// --------------------------- scan2+3 fused: offsets + cursor ---------------
__global__ void k_scan3(int n, int e) {
    __shared__ int sh[256];
    int b = blockIdx.x, t = threadIdx.x;
    int acc = 0;
    for (int j = t; j < b; j += 256) acc += g_bsum[j];
    sh[t] = acc;
    __syncthreads();
#pragma unroll
    for (int off = 128; off > 0; off >>= 1) {
        if (t < off) sh[t] += sh[t + off];
        __syncthreads();
    }
    int offset = sh[0];
    int i = b * 256 + t;
    if (i < n) {
        int r = g_rowptr[i] + offset;
        g_rowptr[i] = r;
        g_cursor[i] = r;
    }
    if (b == 0 && t == 0) g_rowptr[n] = e;
}

// --------------------------- CSR fill (4 edges/thread) ---------------------
__global__ void k_fill(const int* __restrict__ src,
                       const int* __restrict__ dst, int e) {
    int i = (blockIdx.x * blockDim.x + threadIdx.x) * 4;
    if (i + 3 < e) {
        int4 s = *reinterpret_cast<const int4*>(src + i);
        int4 d = *reinterpret_cast<const int4*>(dst + i);
        g_csr[atomicAdd(&g_cursor[d.x], 1)] = s.x;
        g_csr[atomicAdd(&g_cursor[d.y], 1)] = s.y;
        g_csr[atomicAdd(&g_cursor[d.z], 1)] = s.z;
        g_csr[atomicAdd(&g_cursor[d.w], 1)] = s.w;
    } else {
        for (; i < e; i++)
            g_csr[atomicAdd(&g_cursor[dst[i]], 1)] = src[i];
    }
}

// --------------------------- packed f32x2 helpers --------------------------
__device__ __forceinline__ unsigned long long pk2(float x) {
    unsigned long long r;
    asm("mov.b64 %0, {%1, %1};" : "=l"(r) : "f"(x));
    return r;
}
__device__ __forceinline__ void ffma2(unsigned long long& d,
                                      unsigned long long a,
                                      unsigned long long b) {
    asm("fma.rn.f32x2 %0, %1, %2, %0;" : "+l"(d) : "l"(a), "l"(b));
}
__device__ __forceinline__ float2 up2(unsigned long long v) {
    float2 r;
    asm("mov.b64 {%0, %1}, %2;" : "=f"(r.x), "=f"(r.y) : "l"(v));
    return r;
}

// --------------------------- GEMM ------------------------------------------
// 4 threads/node, 16 cols each (8 f32x2 accumulators) -> ~40 regs, high occ.
// FIRST: fp32 raw x input. !FIRST: fp16 g_h input.
// Epilogue: * dis, store fp16 to g_s. No bias/relu (done in gather).
template<bool FIRST>
__global__ void __launch_bounds__(256, 4)
k_gemm(const float* __restrict__ in, const __half* __restrict__ in_h,
       const float* __restrict__ W, int n) {
    __shared__ ulonglong2 Ws2[64 * 16];
    {
        const float4* W4 = reinterpret_cast<const float4*>(W);
        float4* S4 = reinterpret_cast<float4*>(Ws2);
#pragma unroll
        for (int i = threadIdx.x; i < 64 * 16; i += 256) S4[i] = W4[i];
    }
    __syncthreads();

    int gid  = blockIdx.x * 256 + threadIdx.x;
    int node = gid >> 2;
    int q    = gid & 3;                       // cols [q*16, q*16+16)
    if (node >= n) return;

    float dn = g_dis[node];

    unsigned long long acc[8];
#pragma unroll
    for (int j = 0; j < 8; j++) acc[j] = 0ull;

    if (FIRST) {
        const float4* xr = reinterpret_cast<const float4*>(in + (long)node * 64);
#pragma unroll 4
        for (int k4 = 0; k4 < 16; k4++) {
            float4 xv = __ldg(xr + k4);
            const float xs[4] = {xv.x, xv.y, xv.z, xv.w};
#pragma unroll
            for (int kk = 0; kk < 4; kk++) {
                int k = k4 * 4 + kk;
                unsigned long long p = pk2(xs[kk]);
#pragma unroll
                for (int j = 0; j < 4; j++) {
                    ulonglong2 w = Ws2[k * 16 + q * 4 + j];
                    ffma2(acc[2 * j],     p, w.x);
                    ffma2(acc[2 * j + 1], p, w.y);
                }
            }
        }
    } else {
        const uint4* xr = reinterpret_cast<const uint4*>(in_h + (long)node * 64);
#pragma unroll 2
        for (int k8 = 0; k8 < 8; k8++) {
            uint4 qv = __ldg(xr + k8);
            const __half2* h = reinterpret_cast<const __half2*>(&qv);
#pragma unroll
            for (int kk = 0; kk < 4; kk++) {
                float2 f = __half22float2(h[kk]);
                int k = k8 * 8 + kk * 2;
#pragma unroll
                for (int s = 0; s < 2; s++) {
                    unsigned long long p = pk2(s ? f.y : f.x);
#pragma unroll
                    for (int j = 0; j < 4; j++) {
                        ulonglong2 w = Ws2[(k + s) * 16 + q * 4 + j];
                        ffma2(acc[2 * j],     p, w.x);
                        ffma2(acc[2 * j + 1], p, w.y);
                    }
                }
            }
        }
    }

    __half2 outv[8];
#pragma unroll
    for (int j = 0; j < 8; j++) {
        float2 v = up2(acc[j]);
        v.x *= dn; v.y *= dn;
        outv[j] = __float22half2_rn(v);
    }
    uint4* sp = reinterpret_cast<uint4*>(g_s + (long)node * 64 + q * 16);
    sp[0] = reinterpret_cast<const uint4*>(outv)[0];
    sp[1] = reinterpret_cast<const uint4*>(outv)[1];
}

// --------------------------- CSR gather + relu epilogue --------------------
// h[v] = fp16(relu((s[v] + sum s[u]) * dis[v] + b)), 8 threads/node.
__device__ __forceinline__ void acc8(float2* a, uint4 p) {
    const __half2* h = reinterpret_cast<const __half2*>(&p);
#pragma unroll
    for (int q = 0; q < 4; q++) {
        float2 f = __half22float2(h[q]);
        a[q].x += f.x;
        a[q].y += f.y;
    }
}
__global__ void __launch_bounds__(256)
k_gather(const float* __restrict__ bias, int n) {
    int idx  = blockIdx.x * blockDim.x + threadIdx.x;
    int node = idx >> 3;
    int c    = idx & 7;
    if (node >= n) return;

    int beg = __ldg(g_rowptr + node);
    int end = __ldg(g_rowptr + node + 1);

    const uint4* s8 = reinterpret_cast<const uint4*>(g_s);
    float2 a[4] = {{0,0},{0,0},{0,0},{0,0}};
    acc8(a, s8[(long)node * 8 + c]);           // self loop

    int j = beg;
    for (; j + 4 <= end; j += 4) {
        int u0 = __ldg(g_csr + j);
        int u1 = __ldg(g_csr + j + 1);
        int u2 = __ldg(g_csr + j + 2);
        int u3 = __ldg(g_csr + j + 3);
        uint4 p0 = __ldg(s8 + (long)u0 * 8 + c);
        uint4 p1 = __ldg(s8 + (long)u1 * 8 + c);
        uint4 p2 = __ldg(s8 + (long)u2 * 8 + c);
        uint4 p3 = __ldg(s8 + (long)u3 * 8 + c);
        acc8(a, p0); acc8(a, p1); acc8(a, p2); acc8(a, p3);
    }
    for (; j < end; j++) {
        int u = __ldg(g_csr + j);
        acc8(a, __ldg(s8 + (long)u * 8 + c));
    }

    float dn = g_dis[node];
    float4 b0 = __ldg(reinterpret_cast<const float4*>(bias) + c * 2);
    float4 b1 = __ldg(reinterpret_cast<const float4*>(bias) + c * 2 + 1);

    __half2 out[4];
    out[0] = __floats2half2_rn(fmaxf(fmaf(a[0].x, dn, b0.x), 0.0f),
                               fmaxf(fmaf(a[0].y, dn, b0.y), 0.0f));
    out[1] = __floats2half2_rn(fmaxf(fmaf(a[1].x, dn, b0.z), 0.0f),
                               fmaxf(fmaf(a[1].y, dn, b0.w), 0.0f));
    out[2] = __floats2half2_rn(fmaxf(fmaf(a[2].x, dn, b1.x), 0.0f),
                               fmaxf(fmaf(a[2].y, dn, b1.y), 0.0f));
    out[3] = __floats2half2_rn(fmaxf(fmaf(a[3].x, dn, b1.z), 0.0f),
                               fmaxf(fmaf(a[3].y, dn, b1.w), 0.0f));
    reinterpret_cast<uint4*>(g_h)[(long)node * 8 + c] =
        *reinterpret_cast<uint4*>(out);
}

// --------------------------- pool ------------------------------------------
__global__ void __launch_bounds__(256)
k_pool(const int* __restrict__ gids, int n) {
    int t = threadIdx.x;
    int c = t & 7;
    int r = t >> 3;                            // 0..31
    int base = blockIdx.x * 256;
    int lim = base + 256 < n ? base + 256 : n;

    int cur = -1;
    float s[8] = {0, 0, 0, 0, 0, 0, 0, 0};
    for (int i = base + r; i < lim; i += 32) {
        int g = __ldg(gids + i);
        uint4 p = *reinterpret_cast<const uint4*>(g_h + (long)i * 64 + c * 8);
        const __half2* h = reinterpret_cast<const __half2*>(&p);
        float f[8];
#pragma unroll
        for (int q = 0; q < 4; q++) {
            float2 v = __half22float2(h[q]);
            f[2 * q] = v.x; f[2 * q + 1] = v.y;
        }
        if (g != cur) {
            if (cur >= 0)
#pragma unroll
                for (int q = 0; q < 8; q++)
                    atomicAdd(&g_pool[cur * 64 + c * 8 + q], s[q]);
            cur = g;
#pragma unroll
            for (int q = 0; q < 8; q++) s[q] = f[q];
        } else {
#pragma unroll
            for (int q = 0; q < 8; q++) s[q] += f[q];
        }
    }
    if (cur >= 0)
#pragma unroll
        for (int q = 0; q < 8; q++)
            atomicAdd(&g_pool[cur * 64 + c * 8 + q], s[q]);
}

// --------------------------- head MLP --------------------------------------
__global__ void k_head(const float* __restrict__ gfeat,
                       const float* __restrict__ gw, const float* __restrict__ gb,
                       const float* __restrict__ l1w, const float* __restrict__ l1b,
                       const float* __restrict__ l2w, const float* __restrict__ l2b,
                       const float* __restrict__ l3w, const float* __restrict__ l3b,
                       const float* __restrict__ l4w, const float* __restrict__ l4b,
                       float* __restrict__ out) {
    __shared__ float A[64][97];
    __shared__ float Bm[64][65];
    int t = threadIdx.x;

    for (int e = t; e < 64 * 64; e += 256) {          // z1
        int i = e >> 6, j = e & 63;
        float sum = l1b[j];
        for (int k = 0; k < 64; k++) sum = fmaf(g_pool[i * 64 + k], __ldg(l1w + k * 64 + j), sum);
        A[i][j] = fmaxf(sum, 0.0f);
    }
    for (int e = t; e < 64 * 32; e += 256) {          // gx
        int i = e >> 5, j = e & 31;
        float sum = gb[j];
        for (int k = 0; k < 32; k++) sum = fmaf(__ldg(gfeat + i * 32 + k), __ldg(gw + k * 32 + j), sum);
        A[i][64 + j] = fmaxf(sum, 0.0f);
    }
    __syncthreads();
    for (int e = t; e < 64 * 64; e += 256) {          // z2
        int i = e >> 6, j = e & 63;
        float sum = l2b[j];
        for (int k = 0; k < 96; k++) sum = fmaf(A[i][k], __ldg(l2w + k * 64 + j), sum);
        Bm[i][j] = fmaxf(sum, 0.0f);
    }
    __syncthreads();
    for (int e = t; e < 64 * 64; e += 256) {          // z3
        int i = e >> 6, j = e & 63;
        float sum = l3b[j];
        for (int k = 0; k < 64; k++) sum = fmaf(Bm[i][k], __ldg(l3w + k * 64 + j), sum);
        A[i][j] = fmaxf(sum, 0.0f);
    }
    __syncthreads();
    if (t < 64) {
        float sum = l4b[0];
        for (int k = 0; k < 64; k++) sum = fmaf(A[t][k], __ldg(l4w + k), sum);
        out[t] = sum;
    }
}

// ---------------------------------------------------------------------------
extern "C" void kernel_launch(void* const* d_in, const int* in_sizes, int n_in,
                              void* d_out, int out_size) {
    const float* x     = (const float*)d_in[0];
    const float* gfeat = (const float*)d_in[1];
    const float* cw[3] = {(const float*)d_in[2], (const float*)d_in[4], (const float*)d_in[6]};
    const float* cb[3] = {(const float*)d_in[3], (const float*)d_in[5], (const float*)d_in[7]};
    const float* l1w = (const float*)d_in[8];
    const float* l1b = (const float*)d_in[9];
    const float* gw  = (const float*)d_in[10];
    const float* gb  = (const float*)d_in[11];
    const float* l2w = (const float*)d_in[12];
    const float* l2b = (const float*)d_in[13];
    const float* l3w = (const float*)d_in[14];
    const float* l3b = (const float*)d_in[15];
    const float* l4w = (const float*)d_in[16];
    const float* l4b = (const float*)d_in[17];
    const int*   ei   = (const int*)d_in[18];
    const int*   gids = (const int*)d_in[19];
    float* out = (float*)d_out;

    int N = in_sizes[19];
    int E = in_sizes[18] / 2;
    const int* src = ei;
    const int* dst = ei + E;

    void* hp = nullptr;
    cudaGetSymbolAddress(&hp, g_h);
    const __half* h_in = (const __half*)hp;

    const int T = 256;
    int nb_n  = (N + T - 1) / T;
    int nb_e4 = (E / 4 + T - 1) / T;
    int nb_4n = (4 * N + T - 1) / T;
    int nb_8n = (8 * N + T - 1) / T;

    cudaStream_t s1;
    cudaStreamCreate(&s1);
    cudaEvent_t e1, e2;
    cudaEventCreateWithFlags(&e1, cudaEventDisableTiming);
    cudaEventCreateWithFlags(&e2, cudaEventDisableTiming);

    // main chain: zero -> degc -> scan1
    k_zero <<<nb_n, T>>>(N);
    k_degc <<<nb_e4, T>>>(dst, E);
    k_scan1<<<nb_n, T>>>(N);
    cudaEventRecord(e1, 0);

    // side stream: gemm0 (needs only dis), overlapped with CSR finish
    cudaStreamWaitEvent(s1, e1, 0);
    k_gemm<true><<<nb_4n, T, 0, s1>>>(x, nullptr, cw[0], N);
    cudaEventRecord(e2, s1);

    // main chain: finish CSR
    k_scan3<<<nb_n, T>>>(N, E);
    k_fill <<<nb_e4, T>>>(src, dst, E);
    cudaStreamWaitEvent(0, e2, 0);

    // layers
    k_gather<<<nb_8n, T>>>(cb[0], N);
    k_gemm<false><<<nb_4n, T>>>(nullptr, h_in, cw[1], N);
    k_gather<<<nb_8n, T>>>(cb[1], N);
    k_gemm<false><<<nb_4n, T>>>(nullptr, h_in, cw[2], N);
    k_gather<<<nb_8n, T>>>(cb[2], N);

    // pool + head
    k_pool<<<nb_n, T>>>(gids, N);
    k_head<<<1, T>>>(gfeat, gw, gb, l1w, l1b, l2w, l2b, l3w, l3b, l4w, l4b, out);

    cudaEventDestroy(e1);
    cudaEventDestroy(e2);
    cudaStreamDestroy(s1);
}

// round 9
// speedup vs baseline: 1.4111x; 1.4111x over previous
#include <cuda_runtime.h>
#include <cuda_fp16.h>

// ---------------------------------------------------------------------------
// SimpleGCN, sm_100a. fp32 compute, fp16 messages AND activations.
//   s[n] = fp16( (h_in @ W)[n] * dis[n] )            k_gemm   (g_h/x -> g_s)
//   h[v] = fp16( relu( (s[v]+sum s[u]) * dis + b ) ) k_gather (g_s -> g_h)
// GEMM: one thread = 2 nodes x 16 cols (node-paired W reuse + high occupancy).
// ---------------------------------------------------------------------------

#define NN 100000
#define EE 1600000
#define GG 64

__device__ float  g_dis [NN];
__device__ int    g_degi[NN];
__device__ int    g_rowptr[NN + 1];
__device__ int    g_cursor[NN];
__device__ int    g_bsum[512];
__device__ int    g_csr[EE];
__device__ __half g_s [NN * 64];      // fp16 message rows (gemm out)
__device__ __half g_h [NN * 64];      // fp16 activations   (gather out)
__device__ float  g_pool[GG * 64];

// --------------------------- zero (degi + pool) ----------------------------
__global__ void k_zero(int n) {
    int i = blockIdx.x * blockDim.x + threadIdx.x;
    if (i < n) g_degi[i] = 0;
    if (i < GG * 64) g_pool[i] = 0.0f;
}

// --------------------------- degree count (4 edges/thread) -----------------
__global__ void k_degc(const int* __restrict__ dst, int e) {
    int i = (blockIdx.x * blockDim.x + threadIdx.x) * 4;
    if (i + 3 < e) {
        int4 d = *reinterpret_cast<const int4*>(dst + i);
        atomicAdd(&g_degi[d.x], 1);
        atomicAdd(&g_degi[d.y], 1);
        atomicAdd(&g_degi[d.z], 1);
        atomicAdd(&g_degi[d.w], 1);
    } else {
        for (; i < e; i++) atomicAdd(&g_degi[dst[i]], 1);
    }
}

// --------------------------- scan1: block-local scan + dis -----------------
__global__ void k_scan1(int n) {
    __shared__ int s[256];
    int b = blockIdx.x, t = threadIdx.x;
    int i = b * 256 + t;
    int v = (i < n) ? g_degi[i] : 0;
    if (i < n) g_dis[i] = rsqrtf((float)v + 1.0f);
    s[t] = v;
    __syncthreads();
#pragma unroll
    for (int off = 1; off < 256; off <<= 1) {
        int add = (t >= off) ? s[t - off] : 0;
        __syncthreads();
        s[t] += add;
        __syncthreads();
    }
    if (i < n) g_rowptr[i] = s[t] - v;
    if (t == 255) g_bsum[b] = s[255];
}

// --------------------------- scan2+3 fused: offsets + cursor ---------------
__global__ void k_scan3(int n, int e) {
    __shared__ int sh[256];
    int b = blockIdx.x, t = threadIdx.x;
    int acc = 0;
    for (int j = t; j < b; j += 256) acc += g_bsum[j];
    sh[t] = acc;
    __syncthreads();
#pragma unroll
    for (int off = 128; off > 0; off >>= 1) {
        if (t < off) sh[t] += sh[t + off];
        __syncthreads();
    }
    int offset = sh[0];
    int i = b * 256 + t;
    if (i < n) {
        int r = g_rowptr[i] + offset;
        g_rowptr[i] = r;
        g_cursor[i] = r;
    }
    if (b == 0 && t == 0) g_rowptr[n] = e;
}

// --------------------------- CSR fill (4 edges/thread) ---------------------
__global__ void k_fill(const int* __restrict__ src,
                       const int* __restrict__ dst, int e) {
    int i = (blockIdx.x * blockDim.x + threadIdx.x) * 4;
    if (i + 3 < e) {
        int4 s = *reinterpret_cast<const int4*>(src + i);
        int4 d = *reinterpret_cast<const int4*>(dst + i);
        g_csr[atomicAdd(&g_cursor[d.x], 1)] = s.x;
        g_csr[atomicAdd(&g_cursor[d.y], 1)] = s.y;
        g_csr[atomicAdd(&g_cursor[d.z], 1)] = s.z;
        g_csr[atomicAdd(&g_cursor[d.w], 1)] = s.w;
    } else {
        for (; i < e; i++)
            g_csr[atomicAdd(&g_cursor[dst[i]], 1)] = src[i];
    }
}

// --------------------------- packed f32x2 helpers --------------------------
__device__ __forceinline__ unsigned long long pk2(float x) {
    unsigned long long r;
    asm("mov.b64 %0, {%1, %1};" : "=l"(r) : "f"(x));
    return r;
}
__device__ __forceinline__ void ffma2(unsigned long long& d,
                                      unsigned long long a,
                                      unsigned long long b) {
    asm("fma.rn.f32x2 %0, %1, %2, %0;" : "+l"(d) : "l"(a), "l"(b));
}
__device__ __forceinline__ float2 up2(unsigned long long v) {
    float2 r;
    asm("mov.b64 {%0, %1}, %2;" : "=f"(r.x), "=f"(r.y) : "l"(v));
    return r;
}

// --------------------------- GEMM ------------------------------------------
// One thread = 2 nodes x 16 cols (q = gid&3 selects the 16-col group).
// Each 16B LDS of W feeds 8 FFMA2 (2 words x 2 nodes). ~60 regs, occ 4 CTAs.
// FIRST: fp32 raw x. !FIRST: fp16 g_h. Epilogue: * dis, fp16 store to g_s.
template<bool FIRST>
__global__ void __launch_bounds__(256, 4)
k_gemm(const float* __restrict__ in, const __half* __restrict__ in_h,
       const float* __restrict__ W, int n) {
    __shared__ ulonglong2 Ws2[64 * 16];
    {
        const float4* W4 = reinterpret_cast<const float4*>(W);
        float4* S4 = reinterpret_cast<float4*>(Ws2);
#pragma unroll
        for (int i = threadIdx.x; i < 64 * 16; i += 256) S4[i] = W4[i];
    }
    __syncthreads();

    int gid  = blockIdx.x * 256 + threadIdx.x;
    int pair = gid >> 2;
    int q    = gid & 3;                        // cols [q*16, q*16+16)
    int n0 = pair * 2;
    int n1 = n0 + 1;
    if (n0 >= n) return;
    bool has1 = (n1 < n);

    float d0 = g_dis[n0];
    float d1 = has1 ? g_dis[n1] : 0.0f;

    unsigned long long a0[8], a1[8];
#pragma unroll
    for (int j = 0; j < 8; j++) { a0[j] = 0ull; a1[j] = 0ull; }

    if (FIRST) {
        const float4* x0 = reinterpret_cast<const float4*>(in + (long)n0 * 64);
        const float4* x1 = reinterpret_cast<const float4*>(in + (long)n1 * 64);
#pragma unroll 4
        for (int k4 = 0; k4 < 16; k4++) {
            float4 v0 = __ldg(x0 + k4);
            float4 v1 = has1 ? __ldg(x1 + k4) : make_float4(0, 0, 0, 0);
            const float xs0[4] = {v0.x, v0.y, v0.z, v0.w};
            const float xs1[4] = {v1.x, v1.y, v1.z, v1.w};
#pragma unroll
            for (int kk = 0; kk < 4; kk++) {
                int k = k4 * 4 + kk;
                unsigned long long p0 = pk2(xs0[kk]);
                unsigned long long p1 = pk2(xs1[kk]);
#pragma unroll
                for (int j = 0; j < 4; j++) {
                    ulonglong2 w = Ws2[k * 16 + q * 4 + j];
                    ffma2(a0[2 * j],     p0, w.x);
                    ffma2(a0[2 * j + 1], p0, w.y);
                    ffma2(a1[2 * j],     p1, w.x);
                    ffma2(a1[2 * j + 1], p1, w.y);
                }
            }
        }
    } else {
        const uint4* x0 = reinterpret_cast<const uint4*>(in_h + (long)n0 * 64);
        const uint4* x1 = reinterpret_cast<const uint4*>(in_h + (long)n1 * 64);
#pragma unroll 2
        for (int k8 = 0; k8 < 8; k8++) {
            uint4 q0 = __ldg(x0 + k8);
            uint4 q1 = has1 ? __ldg(x1 + k8) : make_uint4(0, 0, 0, 0);
            const __half2* h0 = reinterpret_cast<const __half2*>(&q0);
            const __half2* h1 = reinterpret_cast<const __half2*>(&q1);
#pragma unroll
            for (int kk = 0; kk < 4; kk++) {
                float2 f0 = __half22float2(h0[kk]);
                float2 f1 = __half22float2(h1[kk]);
                int k = k8 * 8 + kk * 2;
#pragma unroll
                for (int s = 0; s < 2; s++) {
                    unsigned long long p0 = pk2(s ? f0.y : f0.x);
                    unsigned long long p1 = pk2(s ? f1.y : f1.x);
#pragma unroll
                    for (int j = 0; j < 4; j++) {
                        ulonglong2 w = Ws2[(k + s) * 16 + q * 4 + j];
                        ffma2(a0[2 * j],     p0, w.x);
                        ffma2(a0[2 * j + 1], p0, w.y);
                        ffma2(a1[2 * j],     p1, w.x);
                        ffma2(a1[2 * j + 1], p1, w.y);
                    }
                }
            }
        }
    }

    {
        __half2 outv[8];
#pragma unroll
        for (int j = 0; j < 8; j++) {
            float2 v = up2(a0[j]);
            v.x *= d0; v.y *= d0;
            outv[j] = __float22half2_rn(v);
        }
        uint4* sp = reinterpret_cast<uint4*>(g_s + (long)n0 * 64 + q * 16);
        sp[0] = reinterpret_cast<const uint4*>(outv)[0];
        sp[1] = reinterpret_cast<const uint4*>(outv)[1];
    }
    if (has1) {
        __half2 outv[8];
#pragma unroll
        for (int j = 0; j < 8; j++) {
            float2 v = up2(a1[j]);
            v.x *= d1; v.y *= d1;
            outv[j] = __float22half2_rn(v);
        }
        uint4* sp = reinterpret_cast<uint4*>(g_s + (long)n1 * 64 + q * 16);
        sp[0] = reinterpret_cast<const uint4*>(outv)[0];
        sp[1] = reinterpret_cast<const uint4*>(outv)[1];
    }
}

// --------------------------- CSR gather + relu epilogue --------------------
// h[v] = fp16(relu((s[v] + sum s[u]) * dis[v] + b)), 8 threads/node.
__device__ __forceinline__ void acc8(float2* a, uint4 p) {
    const __half2* h = reinterpret_cast<const __half2*>(&p);
#pragma unroll
    for (int q = 0; q < 4; q++) {
        float2 f = __half22float2(h[q]);
        a[q].x += f.x;
        a[q].y += f.y;
    }
}
__global__ void __launch_bounds__(256)
k_gather(const float* __restrict__ bias, int n) {
    int idx  = blockIdx.x * blockDim.x + threadIdx.x;
    int node = idx >> 3;
    int c    = idx & 7;
    if (node >= n) return;

    int beg = __ldg(g_rowptr + node);
    int end = __ldg(g_rowptr + node + 1);

    const uint4* s8 = reinterpret_cast<const uint4*>(g_s);
    float2 a[4] = {{0,0},{0,0},{0,0},{0,0}};
    acc8(a, s8[(long)node * 8 + c]);           // self loop

    int j = beg;
    for (; j + 4 <= end; j += 4) {
        int u0 = __ldg(g_csr + j);
        int u1 = __ldg(g_csr + j + 1);
        int u2 = __ldg(g_csr + j + 2);
        int u3 = __ldg(g_csr + j + 3);
        uint4 p0 = __ldg(s8 + (long)u0 * 8 + c);
        uint4 p1 = __ldg(s8 + (long)u1 * 8 + c);
        uint4 p2 = __ldg(s8 + (long)u2 * 8 + c);
        uint4 p3 = __ldg(s8 + (long)u3 * 8 + c);
        acc8(a, p0); acc8(a, p1); acc8(a, p2); acc8(a, p3);
    }
    for (; j < end; j++) {
        int u = __ldg(g_csr + j);
        acc8(a, __ldg(s8 + (long)u * 8 + c));
    }

    float dn = g_dis[node];
    float4 b0 = __ldg(reinterpret_cast<const float4*>(bias) + c * 2);
    float4 b1 = __ldg(reinterpret_cast<const float4*>(bias) + c * 2 + 1);

    __half2 out[4];
    out[0] = __floats2half2_rn(fmaxf(fmaf(a[0].x, dn, b0.x), 0.0f),
                               fmaxf(fmaf(a[0].y, dn, b0.y), 0.0f));
    out[1] = __floats2half2_rn(fmaxf(fmaf(a[1].x, dn, b0.z), 0.0f),
                               fmaxf(fmaf(a[1].y, dn, b0.w), 0.0f));
    out[2] = __floats2half2_rn(fmaxf(fmaf(a[2].x, dn, b1.x), 0.0f),
                               fmaxf(fmaf(a[2].y, dn, b1.y), 0.0f));
    out[3] = __floats2half2_rn(fmaxf(fmaf(a[3].x, dn, b1.z), 0.0f),
                               fmaxf(fmaf(a[3].y, dn, b1.w), 0.0f));
    reinterpret_cast<uint4*>(g_h)[(long)node * 8 + c] =
        *reinterpret_cast<uint4*>(out);
}

// --------------------------- pool ------------------------------------------
__global__ void __launch_bounds__(256)
k_pool(const int* __restrict__ gids, int n) {
    int t = threadIdx.x;
    int c = t & 7;
    int r = t >> 3;                            // 0..31
    int base = blockIdx.x * 256;
    int lim = base + 256 < n ? base + 256 : n;

    int cur = -1;
    float s[8] = {0, 0, 0, 0, 0, 0, 0, 0};
    for (int i = base + r; i < lim; i += 32) {
        int g = __ldg(gids + i);
        uint4 p = *reinterpret_cast<const uint4*>(g_h + (long)i * 64 + c * 8);
        const __half2* h = reinterpret_cast<const __half2*>(&p);
        float f[8];
#pragma unroll
        for (int q = 0; q < 4; q++) {
            float2 v = __half22float2(h[q]);
            f[2 * q] = v.x; f[2 * q + 1] = v.y;
        }
        if (g != cur) {
            if (cur >= 0)
#pragma unroll
                for (int q = 0; q < 8; q++)
                    atomicAdd(&g_pool[cur * 64 + c * 8 + q], s[q]);
            cur = g;
#pragma unroll
            for (int q = 0; q < 8; q++) s[q] = f[q];
        } else {
#pragma unroll
            for (int q = 0; q < 8; q++) s[q] += f[q];
        }
    }
    if (cur >= 0)
#pragma unroll
        for (int q = 0; q < 8; q++)
            atomicAdd(&g_pool[cur * 64 + c * 8 + q], s[q]);
}

// --------------------------- head MLP --------------------------------------
__global__ void k_head(const float* __restrict__ gfeat,
                       const float* __restrict__ gw, const float* __restrict__ gb,
                       const float* __restrict__ l1w, const float* __restrict__ l1b,
                       const float* __restrict__ l2w, const float* __restrict__ l2b,
                       const float* __restrict__ l3w, const float* __restrict__ l3b,
                       const float* __restrict__ l4w, const float* __restrict__ l4b,
                       float* __restrict__ out) {
    __shared__ float A[64][97];
    __shared__ float Bm[64][65];
    int t = threadIdx.x;

    for (int e = t; e < 64 * 64; e += 256) {          // z1
        int i = e >> 6, j = e & 63;
        float sum = l1b[j];
        for (int k = 0; k < 64; k++) sum = fmaf(g_pool[i * 64 + k], __ldg(l1w + k * 64 + j), sum);
        A[i][j] = fmaxf(sum, 0.0f);
    }
    for (int e = t; e < 64 * 32; e += 256) {          // gx
        int i = e >> 5, j = e & 31;
        float sum = gb[j];
        for (int k = 0; k < 32; k++) sum = fmaf(__ldg(gfeat + i * 32 + k), __ldg(gw + k * 32 + j), sum);
        A[i][64 + j] = fmaxf(sum, 0.0f);
    }
    __syncthreads();
    for (int e = t; e < 64 * 64; e += 256) {          // z2
        int i = e >> 6, j = e & 63;
        float sum = l2b[j];
        for (int k = 0; k < 96; k++) sum = fmaf(A[i][k], __ldg(l2w + k * 64 + j), sum);
        Bm[i][j] = fmaxf(sum, 0.0f);
    }
    __syncthreads();
    for (int e = t; e < 64 * 64; e += 256) {          // z3
        int i = e >> 6, j = e & 63;
        float sum = l3b[j];
        for (int k = 0; k < 64; k++) sum = fmaf(Bm[i][k], __ldg(l3w + k * 64 + j), sum);
        A[i][j] = fmaxf(sum, 0.0f);
    }
    __syncthreads();
    if (t < 64) {
        float sum = l4b[0];
        for (int k = 0; k < 64; k++) sum = fmaf(A[t][k], __ldg(l4w + k), sum);
        out[t] = sum;
    }
}

// ---------------------------------------------------------------------------
extern "C" void kernel_launch(void* const* d_in, const int* in_sizes, int n_in,
                              void* d_out, int out_size) {
    const float* x     = (const float*)d_in[0];
    const float* gfeat = (const float*)d_in[1];
    const float* cw[3] = {(const float*)d_in[2], (const float*)d_in[4], (const float*)d_in[6]};
    const float* cb[3] = {(const float*)d_in[3], (const float*)d_in[5], (const float*)d_in[7]};
    const float* l1w = (const float*)d_in[8];
    const float* l1b = (const float*)d_in[9];
    const float* gw  = (const float*)d_in[10];
    const float* gb  = (const float*)d_in[11];
    const float* l2w = (const float*)d_in[12];
    const float* l2b = (const float*)d_in[13];
    const float* l3w = (const float*)d_in[14];
    const float* l3b = (const float*)d_in[15];
    const float* l4w = (const float*)d_in[16];
    const float* l4b = (const float*)d_in[17];
    const int*   ei   = (const int*)d_in[18];
    const int*   gids = (const int*)d_in[19];
    float* out = (float*)d_out;

    int N = in_sizes[19];
    int E = in_sizes[18] / 2;
    const int* src = ei;
    const int* dst = ei + E;

    void* hp = nullptr;
    cudaGetSymbolAddress(&hp, g_h);
    const __half* h_in = (const __half*)hp;

    const int T = 256;
    int nb_n  = (N + T - 1) / T;
    int nb_e4 = (E / 4 + T - 1) / T;
    int nb_2n = (2 * N + T - 1) / T;           // gemm: 4 threads per node-pair
    int nb_8n = (8 * N + T - 1) / T;

    cudaStream_t s1;
    cudaStreamCreate(&s1);
    cudaEvent_t e1, e2;
    cudaEventCreateWithFlags(&e1, cudaEventDisableTiming);
    cudaEventCreateWithFlags(&e2, cudaEventDisableTiming);

    // main chain: zero -> degc -> scan1
    k_zero <<<nb_n, T>>>(N);
    k_degc <<<nb_e4, T>>>(dst, E);
    k_scan1<<<nb_n, T>>>(N);
    cudaEventRecord(e1, 0);

    // side stream: gemm0 (needs only dis), overlapped with CSR finish
    cudaStreamWaitEvent(s1, e1, 0);
    k_gemm<true><<<nb_2n, T, 0, s1>>>(x, nullptr, cw[0], N);
    cudaEventRecord(e2, s1);

    // main chain: finish CSR
    k_scan3<<<nb_n, T>>>(N, E);
    k_fill <<<nb_e4, T>>>(src, dst, E);
    cudaStreamWaitEvent(0, e2, 0);

    // layers
    k_gather<<<nb_8n, T>>>(cb[0], N);
    k_gemm<false><<<nb_2n, T>>>(nullptr, h_in, cw[1], N);
    k_gather<<<nb_8n, T>>>(cb[1], N);
    k_gemm<false><<<nb_2n, T>>>(nullptr, h_in, cw[2], N);
    k_gather<<<nb_8n, T>>>(cb[2], N);

    // pool + head
    k_pool<<<nb_n, T>>>(gids, N);
    k_head<<<1, T>>>(gfeat, gw, gb, l1w, l1b, l2w, l2b, l3w, l3b, l4w, l4b, out);

    cudaEventDestroy(e1);
    cudaEventDestroy(e2);
    cudaStreamDestroy(s1);
}

// round 10
// speedup vs baseline: 2.4168x; 1.7127x over previous
#include <cuda_runtime.h>
#include <cuda_fp16.h>
#include <cstdint>

// ---------------------------------------------------------------------------
// SimpleGCN, sm_100a. Tensor-core GEMM (mma.sync m16n8k16, fp16 in / fp32 acc),
// fp16 messages + activations, CSR gather, stream-overlapped preprocessing.
//   s[n] = fp16( (h_in @ W)[n] * dis[n] )            k_mma    (fp16 in -> g_s)
//   h[v] = fp16( relu( (s[v]+sum s[u]) * dis + b ) ) k_gather (g_s -> g_h)
// ---------------------------------------------------------------------------

#define NN 100000
#define EE 1600000
#define GG 64

__device__ float  g_dis [NN];
__device__ int    g_degi[NN];
__device__ int    g_rowptr[NN + 1];
__device__ int    g_cursor[NN];
__device__ int    g_bsum[512];
__device__ int    g_csr[EE];
__device__ __half g_xh[NN * 64];      // fp16 copy of input x
__device__ __half g_s [NN * 64];      // fp16 message rows (mma out)
__device__ __half g_h [NN * 64];      // fp16 activations  (gather out)
__device__ uint2  g_wb[3 * 4 * 8 * 32]; // fragment-packed fp16 W, 3 layers
__device__ float  g_pool[GG * 64];

// --------------------------- zero (degi + pool) ----------------------------
__global__ void k_zero(int n) {
    int i = blockIdx.x * blockDim.x + threadIdx.x;
    if (i < n) g_degi[i] = 0;
    if (i < GG * 64) g_pool[i] = 0.0f;
}

// --------------------------- degree count (4 edges/thread) -----------------
__global__ void k_degc(const int* __restrict__ dst, int e) {
    int i = (blockIdx.x * blockDim.x + threadIdx.x) * 4;
    if (i + 3 < e) {
        int4 d = *reinterpret_cast<const int4*>(dst + i);
        atomicAdd(&g_degi[d.x], 1);
        atomicAdd(&g_degi[d.y], 1);
        atomicAdd(&g_degi[d.z], 1);
        atomicAdd(&g_degi[d.w], 1);
    } else {
        for (; i < e; i++) atomicAdd(&g_degi[dst[i]], 1);
    }
}

// --------------------------- scan1: block-local scan + dis -----------------
__global__ void k_scan1(int n) {
    __shared__ int s[256];
    int b = blockIdx.x, t = threadIdx.x;
    int i = b * 256 + t;
    int v = (i < n) ? g_degi[i] : 0;
    if (i < n) g_dis[i] = rsqrtf((float)v + 1.0f);
    s[t] = v;
    __syncthreads();
#pragma unroll
    for (int off = 1; off < 256; off <<= 1) {
        int add = (t >= off) ? s[t - off] : 0;
        __syncthreads();
        s[t] += add;
        __syncthreads();
    }
    if (i < n) g_rowptr[i] = s[t] - v;
    if (t == 255) g_bsum[b] = s[255];
}

// --------------------------- scan2+3 fused ---------------------------------
__global__ void k_scan3(int n, int e) {
    __shared__ int sh[256];
    int b = blockIdx.x, t = threadIdx.x;
    int acc = 0;
    for (int j = t; j < b; j += 256) acc += g_bsum[j];
    sh[t] = acc;
    __syncthreads();
#pragma unroll
    for (int off = 128; off > 0; off >>= 1) {
        if (t < off) sh[t] += sh[t + off];
        __syncthreads();
    }
    int offset = sh[0];
    int i = b * 256 + t;
    if (i < n) {
        int r = g_rowptr[i] + offset;
        g_rowptr[i] = r;
        g_cursor[i] = r;
    }
    if (b == 0 && t == 0) g_rowptr[n] = e;
}

// --------------------------- CSR fill (4 edges/thread) ---------------------
__global__ void k_fill(const int* __restrict__ src,
                       const int* __restrict__ dst, int e) {
    int i = (blockIdx.x * blockDim.x + threadIdx.x) * 4;
    if (i + 3 < e) {
        int4 s = *reinterpret_cast<const int4*>(src + i);
        int4 d = *reinterpret_cast<const int4*>(dst + i);
        g_csr[atomicAdd(&g_cursor[d.x], 1)] = s.x;
        g_csr[atomicAdd(&g_cursor[d.y], 1)] = s.y;
        g_csr[atomicAdd(&g_cursor[d.z], 1)] = s.z;
        g_csr[atomicAdd(&g_cursor[d.w], 1)] = s.w;
    } else {
        for (; i < e; i++)
            g_csr[atomicAdd(&g_cursor[dst[i]], 1)] = src[i];
    }
}

// --------------------------- x -> fp16 -------------------------------------
__global__ void k_xconv(const float* __restrict__ x, int n8) {
    int i = blockIdx.x * blockDim.x + threadIdx.x;
    if (i >= n8) return;
    const float4* p = reinterpret_cast<const float4*>(x) + (long)i * 2;
    float4 v0 = __ldg(p);
    float4 v1 = __ldg(p + 1);
    __half2 h[4];
    h[0] = __floats2half2_rn(v0.x, v0.y);
    h[1] = __floats2half2_rn(v0.z, v0.w);
    h[2] = __floats2half2_rn(v1.x, v1.y);
    h[3] = __floats2half2_rn(v1.z, v1.w);
    reinterpret_cast<uint4*>(g_xh)[i] = *reinterpret_cast<uint4*>(h);
}

// --------------------------- W -> fp16 B fragments -------------------------
// g_wb[((layer*4+kstep)*8+nt)*32 + lane] = {b0, b1} for mma m16n8k16:
//   b0 halves = W[k0][n], W[k0+1][n]   (k0 = kstep*16 + (lane&3)*2)
//   b1 halves = W[k0+8][n], W[k0+9][n] (n  = nt*8 + (lane>>2))
__global__ void k_wconv(const float* __restrict__ w0,
                        const float* __restrict__ w1,
                        const float* __restrict__ w2) {
    int tid = blockIdx.x * blockDim.x + threadIdx.x;
    if (tid >= 3 * 4 * 8 * 32) return;
    int lane  = tid & 31;
    int nt    = (tid >> 5) & 7;
    int kstep = (tid >> 8) & 3;
    int layer = tid >> 10;
    const float* W = layer == 0 ? w0 : (layer == 1 ? w1 : w2);
    int k0 = kstep * 16 + (lane & 3) * 2;
    int n  = nt * 8 + (lane >> 2);
    __half2 lo = __floats2half2_rn(W[k0 * 64 + n],       W[(k0 + 1) * 64 + n]);
    __half2 hi = __floats2half2_rn(W[(k0 + 8) * 64 + n], W[(k0 + 9) * 64 + n]);
    uint2 v;
    v.x = *reinterpret_cast<uint32_t*>(&lo);
    v.y = *reinterpret_cast<uint32_t*>(&hi);
    g_wb[tid] = v;
}

// --------------------------- tensor-core GEMM ------------------------------
// Warp computes 16 nodes x 64 cols: 4 k-steps x 8 n-tiles of m16n8k16.
// Epilogue: * dis[row], fp16 store to g_s.
__global__ void __launch_bounds__(256)
k_mma(const __half* __restrict__ A, int layer, int n, int ntiles) {
    int warp  = (blockIdx.x * blockDim.x + threadIdx.x) >> 5;
    int lane  = threadIdx.x & 31;
    int nwarps = gridDim.x * (blockDim.x >> 5);

    // W fragments: 64 regs, loaded once per warp
    uint32_t b[4][8][2];
    const uint2* wb = g_wb + layer * 1024;
#pragma unroll
    for (int k = 0; k < 4; k++)
#pragma unroll
        for (int nt = 0; nt < 8; nt++) {
            uint2 v = __ldg(wb + (k * 8 + nt) * 32 + lane);
            b[k][nt][0] = v.x;
            b[k][nt][1] = v.y;
        }

    int gid4 = lane >> 2;            // 0..7
    int tid2 = (lane & 3) * 2;       // 0,2,4,6

    for (int t = warp; t < ntiles; t += nwarps) {
        int base = t * 16;
        int r0 = base + gid4;
        int r1 = r0 + 8;
        int r0l = r0 < n ? r0 : n - 1;
        int r1l = r1 < n ? r1 : n - 1;
        const uint32_t* A0 = reinterpret_cast<const uint32_t*>(A) + (long)r0l * 32;
        const uint32_t* A1 = reinterpret_cast<const uint32_t*>(A) + (long)r1l * 32;

        float c[8][4];
#pragma unroll
        for (int nt = 0; nt < 8; nt++) {
            c[nt][0] = 0.f; c[nt][1] = 0.f; c[nt][2] = 0.f; c[nt][3] = 0.f;
        }

#pragma unroll
        for (int k = 0; k < 4; k++) {
            int kb = k * 8 + (tid2 >> 1);           // u32 index in row
            uint32_t a0 = __ldg(A0 + kb);           // (r0, k cols 0..7 region)
            uint32_t a1 = __ldg(A1 + kb);           // (r1, same)
            uint32_t a2 = __ldg(A0 + kb + 4);       // (r0, +8 cols)
            uint32_t a3 = __ldg(A1 + kb + 4);       // (r1, +8 cols)
#pragma unroll
            for (int nt = 0; nt < 8; nt++) {
                asm volatile(
                    "mma.sync.aligned.m16n8k16.row.col.f32.f16.f16.f32 "
                    "{%0,%1,%2,%3},{%4,%5,%6,%7},{%8,%9},{%0,%1,%2,%3};"
                    : "+f"(c[nt][0]), "+f"(c[nt][1]), "+f"(c[nt][2]), "+f"(c[nt][3])
                    : "r"(a0), "r"(a1), "r"(a2), "r"(a3),
                      "r"(b[k][nt][0]), "r"(b[k][nt][1]));
            }
        }

        float d0 = g_dis[r0l];
        float d1 = g_dis[r1l];
        if (r0 < n) {
            __half2* o = reinterpret_cast<__half2*>(g_s + (long)r0 * 64 + tid2);
#pragma unroll
            for (int nt = 0; nt < 8; nt++)
                o[nt * 4] = __floats2half2_rn(c[nt][0] * d0, c[nt][1] * d0);
        }
        if (r1 < n) {
            __half2* o = reinterpret_cast<__half2*>(g_s + (long)r1 * 64 + tid2);
#pragma unroll
            for (int nt = 0; nt < 8; nt++)
                o[nt * 4] = __floats2half2_rn(c[nt][2] * d1, c[nt][3] * d1);
        }
    }
}

// --------------------------- CSR gather + relu epilogue --------------------
__device__ __forceinline__ void acc8(float2* a, uint4 p) {
    const __half2* h = reinterpret_cast<const __half2*>(&p);
#pragma unroll
    for (int q = 0; q < 4; q++) {
        float2 f = __half22float2(h[q]);
        a[q].x += f.x;
        a[q].y += f.y;
    }
}
__global__ void __launch_bounds__(256)
k_gather(const float* __restrict__ bias, int n) {
    int idx  = blockIdx.x * blockDim.x + threadIdx.x;
    int node = idx >> 3;
    int c    = idx & 7;
    if (node >= n) return;

    int beg = __ldg(g_rowptr + node);
    int end = __ldg(g_rowptr + node + 1);

    const uint4* s8 = reinterpret_cast<const uint4*>(g_s);
    float2 a[4] = {{0,0},{0,0},{0,0},{0,0}};
    acc8(a, s8[(long)node * 8 + c]);           // self loop

    int j = beg;
    for (; j + 4 <= end; j += 4) {
        int u0 = __ldg(g_csr + j);
        int u1 = __ldg(g_csr + j + 1);
        int u2 = __ldg(g_csr + j + 2);
        int u3 = __ldg(g_csr + j + 3);
        uint4 p0 = __ldg(s8 + (long)u0 * 8 + c);
        uint4 p1 = __ldg(s8 + (long)u1 * 8 + c);
        uint4 p2 = __ldg(s8 + (long)u2 * 8 + c);
        uint4 p3 = __ldg(s8 + (long)u3 * 8 + c);
        acc8(a, p0); acc8(a, p1); acc8(a, p2); acc8(a, p3);
    }
    for (; j < end; j++) {
        int u = __ldg(g_csr + j);
        acc8(a, __ldg(s8 + (long)u * 8 + c));
    }

    float dn = g_dis[node];
    float4 b0 = __ldg(reinterpret_cast<const float4*>(bias) + c * 2);
    float4 b1 = __ldg(reinterpret_cast<const float4*>(bias) + c * 2 + 1);

    __half2 out[4];
    out[0] = __floats2half2_rn(fmaxf(fmaf(a[0].x, dn, b0.x), 0.0f),
                               fmaxf(fmaf(a[0].y, dn, b0.y), 0.0f));
    out[1] = __floats2half2_rn(fmaxf(fmaf(a[1].x, dn, b0.z), 0.0f),
                               fmaxf(fmaf(a[1].y, dn, b0.w), 0.0f));
    out[2] = __floats2half2_rn(fmaxf(fmaf(a[2].x, dn, b1.x), 0.0f),
                               fmaxf(fmaf(a[2].y, dn, b1.y), 0.0f));
    out[3] = __floats2half2_rn(fmaxf(fmaf(a[3].x, dn, b1.z), 0.0f),
                               fmaxf(fmaf(a[3].y, dn, b1.w), 0.0f));
    reinterpret_cast<uint4*>(g_h)[(long)node * 8 + c] =
        *reinterpret_cast<uint4*>(out);
}

// --------------------------- pool ------------------------------------------
__global__ void __launch_bounds__(256)
k_pool(const int* __restrict__ gids, int n) {
    int t = threadIdx.x;
    int c = t & 7;
    int r = t >> 3;                            // 0..31
    int base = blockIdx.x * 256;
    int lim = base + 256 < n ? base + 256 : n;

    int cur = -1;
    float s[8] = {0, 0, 0, 0, 0, 0, 0, 0};
    for (int i = base + r; i < lim; i += 32) {
        int g = __ldg(gids + i);
        uint4 p = *reinterpret_cast<const uint4*>(g_h + (long)i * 64 + c * 8);
        const __half2* h = reinterpret_cast<const __half2*>(&p);
        float f[8];
#pragma unroll
        for (int q = 0; q < 4; q++) {
            float2 v = __half22float2(h[q]);
            f[2 * q] = v.x; f[2 * q + 1] = v.y;
        }
        if (g != cur) {
            if (cur >= 0)
#pragma unroll
                for (int q = 0; q < 8; q++)
                    atomicAdd(&g_pool[cur * 64 + c * 8 + q], s[q]);
            cur = g;
#pragma unroll
            for (int q = 0; q < 8; q++) s[q] = f[q];
        } else {
#pragma unroll
            for (int q = 0; q < 8; q++) s[q] += f[q];
        }
    }
    if (cur >= 0)
#pragma unroll
        for (int q = 0; q < 8; q++)
            atomicAdd(&g_pool[cur * 64 + c * 8 + q], s[q]);
}

// --------------------------- head MLP --------------------------------------
__global__ void k_head(const float* __restrict__ gfeat,
                       const float* __restrict__ gw, const float* __restrict__ gb,
                       const float* __restrict__ l1w, const float* __restrict__ l1b,
                       const float* __restrict__ l2w, const float* __restrict__ l2b,
                       const float* __restrict__ l3w, const float* __restrict__ l3b,
                       const float* __restrict__ l4w, const float* __restrict__ l4b,
                       float* __restrict__ out) {
    __shared__ float A[64][97];
    __shared__ float Bm[64][65];
    int t = threadIdx.x;

    for (int e = t; e < 64 * 64; e += 256) {          // z1
        int i = e >> 6, j = e & 63;
        float sum = l1b[j];
        for (int k = 0; k < 64; k++) sum = fmaf(g_pool[i * 64 + k], __ldg(l1w + k * 64 + j), sum);
        A[i][j] = fmaxf(sum, 0.0f);
    }
    for (int e = t; e < 64 * 32; e += 256) {          // gx
        int i = e >> 5, j = e & 31;
        float sum = gb[j];
        for (int k = 0; k < 32; k++) sum = fmaf(__ldg(gfeat + i * 32 + k), __ldg(gw + k * 32 + j), sum);
        A[i][64 + j] = fmaxf(sum, 0.0f);
    }
    __syncthreads();
    for (int e = t; e < 64 * 64; e += 256) {          // z2
        int i = e >> 6, j = e & 63;
        float sum = l2b[j];
        for (int k = 0; k < 96; k++) sum = fmaf(A[i][k], __ldg(l2w + k * 64 + j), sum);
        Bm[i][j] = fmaxf(sum, 0.0f);
    }
    __syncthreads();
    for (int e = t; e < 64 * 64; e += 256) {          // z3
        int i = e >> 6, j = e & 63;
        float sum = l3b[j];
        for (int k = 0; k < 64; k++) sum = fmaf(Bm[i][k], __ldg(l3w + k * 64 + j), sum);
        A[i][j] = fmaxf(sum, 0.0f);
    }
    __syncthreads();
    if (t < 64) {
        float sum = l4b[0];
        for (int k = 0; k < 64; k++) sum = fmaf(A[t][k], __ldg(l4w + k), sum);
        out[t] = sum;
    }
}

// ---------------------------------------------------------------------------
extern "C" void kernel_launch(void* const* d_in, const int* in_sizes, int n_in,
                              void* d_out, int out_size) {
    const float* x     = (const float*)d_in[0];
    const float* gfeat = (const float*)d_in[1];
    const float* cw[3] = {(const float*)d_in[2], (const float*)d_in[4], (const float*)d_in[6]};
    const float* cb[3] = {(const float*)d_in[3], (const float*)d_in[5], (const float*)d_in[7]};
    const float* l1w = (const float*)d_in[8];
    const float* l1b = (const float*)d_in[9];
    const float* gw  = (const float*)d_in[10];
    const float* gb  = (const float*)d_in[11];
    const float* l2w = (const float*)d_in[12];
    const float* l2b = (const float*)d_in[13];
    const float* l3w = (const float*)d_in[14];
    const float* l3b = (const float*)d_in[15];
    const float* l4w = (const float*)d_in[16];
    const float* l4b = (const float*)d_in[17];
    const int*   ei   = (const int*)d_in[18];
    const int*   gids = (const int*)d_in[19];
    float* out = (float*)d_out;

    int N = in_sizes[19];
    int E = in_sizes[18] / 2;
    const int* src = ei;
    const int* dst = ei + E;
    int ntiles = (N + 15) / 16;

    void* hp = nullptr;
    cudaGetSymbolAddress(&hp, g_h);
    void* xp = nullptr;
    cudaGetSymbolAddress(&xp, g_xh);
    const __half* h_in = (const __half*)hp;
    const __half* xh_in = (const __half*)xp;

    const int T = 256;
    int nb_n   = (N + T - 1) / T;
    int nb_e4  = (E / 4 + T - 1) / T;
    int nb_8n  = (8 * N + T - 1) / T;
    int nb_x   = (N * 8 + T - 1) / T;
    int nb_mma = 160;

    cudaStream_t s1;
    cudaStreamCreate(&s1);
    cudaEvent_t e1, e2;
    cudaEventCreateWithFlags(&e1, cudaEventDisableTiming);
    cudaEventCreateWithFlags(&e2, cudaEventDisableTiming);

    // side stream: fp16 conversions (no deps on graph structure)
    k_wconv<<<12, T, 0, s1>>>(cw[0], cw[1], cw[2]);
    k_xconv<<<nb_x, T, 0, s1>>>(x, N * 8);

    // main chain: zero -> degc -> scan1 (produces dis)
    k_zero <<<nb_n, T>>>(N);
    k_degc <<<nb_e4, T>>>(dst, E);
    k_scan1<<<nb_n, T>>>(N);
    cudaEventRecord(e1, 0);

    // side stream: gemm layer 0 (needs dis + g_xh + g_wb)
    cudaStreamWaitEvent(s1, e1, 0);
    k_mma<<<nb_mma, T, 0, s1>>>(xh_in, 0, N, ntiles);
    cudaEventRecord(e2, s1);

    // main chain: finish CSR build, overlapped with gemm0
    k_scan3<<<nb_n, T>>>(N, E);
    k_fill <<<nb_e4, T>>>(src, dst, E);
    cudaStreamWaitEvent(0, e2, 0);

    // layers
    k_gather<<<nb_8n, T>>>(cb[0], N);
    k_mma<<<nb_mma, T>>>(h_in, 1, N, ntiles);
    k_gather<<<nb_8n, T>>>(cb[1], N);
    k_mma<<<nb_mma, T>>>(h_in, 2, N, ntiles);
    k_gather<<<nb_8n, T>>>(cb[2], N);

    // pool + head
    k_pool<<<nb_n, T>>>(gids, N);
    k_head<<<1, T>>>(gfeat, gw, gb, l1w, l1b, l2w, l2b, l3w, l3b, l4w, l4b, out);

    cudaEventDestroy(e1);
    cudaEventDestroy(e2);
    cudaStreamDestroy(s1);
}